// round 2
// baseline (speedup 1.0000x reference)
#include <cuda_runtime.h>
#include <cuda_bf16.h>

// LocalCrossLinearTrf: B=2, D=H=W=64, F_IN=F_OUT=8
//   x    [2,64,64,64,8]         4,194,304 f32
//   mult [64,64,64,8,8]        16,777,216 f32
//   trf  [64,64,64,8,8,3]      50,331,648 f32
//   bias [64,64,64,8]           2,097,152 f32
//   out  [2,64,64,64,8]         4,194,304 f32
//
// Per voxel v, output j:
//   y[b,v,j] = sum_i mult[v,i,j] * trilerp(x[b], grid(v)+trf[v,i,j], ch=i) + 8*bias[v,j]
// Corner convention (neurite): for axis bit c: index = (c ? l1 : l0),
// weight factor = (c ? d0 : d1) with d1 = l1 - clip(loc), d0 = 1 - d1.

#define NVOX   262144        // 64^3
#define XB     2097152       // per-batch x/out stride (64^3 * 8)
#define SD     32768         // D stride in x (64*64*8)
#define SH     512           // H stride in x (64*8)
#define SW     8             // W stride in x

constexpr int VPB = 32;      // voxels per block
constexpr int THREADS = 256; // 8 threads (one per j) per voxel

__global__ __launch_bounds__(THREADS)
void lclt_kernel(const float* __restrict__ x,
                 const float* __restrict__ mult,
                 const float* __restrict__ trf,
                 const float* __restrict__ bias,
                 float* __restrict__ out)
{
    __shared__ float s_trf [VPB * 192];  // [vl][i*24 + j*3 + a]
    __shared__ float s_mult[VPB * 64];   // [vl][i*8 + j]
    __shared__ float s_bias[VPB * 8];    // [vl][j]

    const int vbase = blockIdx.x * VPB;

    // ---- coalesced staging (float4) ----
    {
        const float4* gt = reinterpret_cast<const float4*>(trf + (size_t)vbase * 192);
        float4* st = reinterpret_cast<float4*>(s_trf);
        #pragma unroll
        for (int k = threadIdx.x; k < VPB * 192 / 4; k += THREADS) st[k] = gt[k];

        const float4* gm = reinterpret_cast<const float4*>(mult + (size_t)vbase * 64);
        float4* sm = reinterpret_cast<float4*>(s_mult);
        #pragma unroll
        for (int k = threadIdx.x; k < VPB * 64 / 4; k += THREADS) sm[k] = gm[k];

        s_bias[threadIdx.x] = bias[(size_t)vbase * 8 + threadIdx.x];
    }
    __syncthreads();

    const int vl = threadIdx.x >> 3;   // local voxel 0..31
    const int j  = threadIdx.x & 7;    // output feature
    const int v  = vbase + vl;
    const int wc =  v        & 63;
    const int hc = (v >> 6)  & 63;
    const int dc =  v >> 12;
    const float fd = (float)dc, fh = (float)hc, fw = (float)wc;

    const float* tb = s_trf  + vl * 192 + j * 3;
    const float* mb = s_mult + vl * 64  + j;
    const float* x1 = x + XB;

    float acc0 = 0.f, acc1 = 0.f;

    #pragma unroll
    for (int i = 0; i < 8; ++i) {
        const float t0 = tb[i * 24 + 0];
        const float t1 = tb[i * 24 + 1];
        const float t2 = tb[i * 24 + 2];
        const float m  = mb[i * 8];

        // --- per-axis corner indices + weights ---
        // axis D
        float loc = fd + t0;
        float cl  = fminf(fmaxf(loc, 0.f), 63.f);
        int   l0  = (int)fminf(fmaxf(floorf(loc), 0.f), 63.f);
        int   l1  = min(l0 + 1, 63);
        float d1d = (float)l1 - cl;
        float d0d = 1.f - d1d;
        int   oD0 = l0 * SD, oD1 = l1 * SD;
        // axis H
        loc = fh + t1;
        cl  = fminf(fmaxf(loc, 0.f), 63.f);
        l0  = (int)fminf(fmaxf(floorf(loc), 0.f), 63.f);
        l1  = min(l0 + 1, 63);
        float d1h = (float)l1 - cl;
        float d0h = 1.f - d1h;
        int   oH0 = l0 * SH, oH1 = l1 * SH;
        // axis W
        loc = fw + t2;
        cl  = fminf(fmaxf(loc, 0.f), 63.f);
        l0  = (int)fminf(fmaxf(floorf(loc), 0.f), 63.f);
        l1  = min(l0 + 1, 63);
        float d1w = (float)l1 - cl;
        float d0w = 1.f - d1w;
        int   oW0 = l0 * SW + i, oW1 = l1 * SW + i;

        // combined DH weights / offsets (c=0 -> l0 with weight d1; c=1 -> l1 with weight d0)
        const float w00 = d1d * d1h, w01 = d1d * d0h, w10 = d0d * d1h, w11 = d0d * d0h;
        const int   o00 = oD0 + oH0, o01 = oD0 + oH1, o10 = oD1 + oH0, o11 = oD1 + oH1;

        float s0 = 0.f, s1 = 0.f;
        {
            float wl, wr; int il, ir;
            wl = w00 * d1w; wr = w00 * d0w; il = o00 + oW0; ir = o00 + oW1;
            s0 = fmaf(wl, __ldg(x  + il), s0); s0 = fmaf(wr, __ldg(x  + ir), s0);
            s1 = fmaf(wl, __ldg(x1 + il), s1); s1 = fmaf(wr, __ldg(x1 + ir), s1);
            wl = w01 * d1w; wr = w01 * d0w; il = o01 + oW0; ir = o01 + oW1;
            s0 = fmaf(wl, __ldg(x  + il), s0); s0 = fmaf(wr, __ldg(x  + ir), s0);
            s1 = fmaf(wl, __ldg(x1 + il), s1); s1 = fmaf(wr, __ldg(x1 + ir), s1);
            wl = w10 * d1w; wr = w10 * d0w; il = o10 + oW0; ir = o10 + oW1;
            s0 = fmaf(wl, __ldg(x  + il), s0); s0 = fmaf(wr, __ldg(x  + ir), s0);
            s1 = fmaf(wl, __ldg(x1 + il), s1); s1 = fmaf(wr, __ldg(x1 + ir), s1);
            wl = w11 * d1w; wr = w11 * d0w; il = o11 + oW0; ir = o11 + oW1;
            s0 = fmaf(wl, __ldg(x  + il), s0); s0 = fmaf(wr, __ldg(x  + ir), s0);
            s1 = fmaf(wl, __ldg(x1 + il), s1); s1 = fmaf(wr, __ldg(x1 + ir), s1);
        }

        acc0 = fmaf(m, s0, acc0);
        acc1 = fmaf(m, s1, acc1);
    }

    const float bterm = 8.f * s_bias[vl * 8 + j];
    const int oidx = v * 8 + j;
    out[oidx]      = acc0 + bterm;
    out[oidx + XB] = acc1 + bterm;
}

extern "C" void kernel_launch(void* const* d_in, const int* in_sizes, int n_in,
                              void* d_out, int out_size)
{
    const float* x    = (const float*)d_in[0];
    const float* mult = (const float*)d_in[1];
    const float* trf  = (const float*)d_in[2];
    const float* bias = (const float*)d_in[3];
    float* out = (float*)d_out;

    dim3 grid(NVOX / VPB);  // 8192 blocks
    lclt_kernel<<<grid, THREADS>>>(x, mult, trf, bias, out);
}